// round 5
// baseline (speedup 1.0000x reference)
#include <cuda_runtime.h>

// DempsterSchaferCombine — algebraically reduced to a pure elementwise stream:
//   out = (a1-1)*(a2-1)/21 + a1 + a2 - 1
// (Dirichlet strengths S1,S2 and the conflict denom cancel exactly; rel_err
// vs the full reference path is ~8e-8.)
//
// R5: single-wave launch (1216 blocks = 152 SM x 8) with a light grid-stride
// loop over 512-float4 chunks, eliminating the 0.68-fill tail wave of the
// 21504-block one-shot grid. Loop body keeps the R4 shape: 2 block-contiguous
// float4/thread, 4 independent LDG.128.CS front-batched, regs <= 32 so
// occupancy stays at 2048 thr/SM. Because n4 is a multiple of 512, each
// existing chunk is complete -> one predicate per iteration.

#define INV_C (1.0f / 21.0f)

__device__ __forceinline__ float4 ds4(float4 x, float4 y) {
    float4 r;
    r.x = fmaf((x.x - 1.0f) * (y.x - 1.0f), INV_C, x.x + y.x - 1.0f);
    r.y = fmaf((x.y - 1.0f) * (y.y - 1.0f), INV_C, x.y + y.y - 1.0f);
    r.z = fmaf((x.z - 1.0f) * (y.z - 1.0f), INV_C, x.z + y.z - 1.0f);
    r.w = fmaf((x.w - 1.0f) * (y.w - 1.0f), INV_C, x.w + y.w - 1.0f);
    return r;
}

// Requires n4 % 512 == 0 (every chunk complete; single predicate per chunk).
__global__ __launch_bounds__(256, 8) void ds_combine_wave(
    const float4* __restrict__ a1,
    const float4* __restrict__ a2,
    float4* __restrict__ out,
    int n4)
{
    const int step = gridDim.x * 512;          // f4 per full wave
    for (int i0 = blockIdx.x * 512 + threadIdx.x; i0 < n4; i0 += step) {
        int i1 = i0 + 256;                      // same chunk, always in range
        float4 x0 = __ldcs(a1 + i0);
        float4 x1 = __ldcs(a1 + i1);
        float4 y0 = __ldcs(a2 + i0);
        float4 y1 = __ldcs(a2 + i1);
        __stcs(out + i0, ds4(x0, y0));
        __stcs(out + i1, ds4(x1, y1));
    }
}

// Fully-guarded fallback for shapes where n4 % 512 != 0.
__global__ __launch_bounds__(256, 8) void ds_combine_guarded(
    const float4* __restrict__ a1,
    const float4* __restrict__ a2,
    float4* __restrict__ out,
    int n4)
{
    int i0 = blockIdx.x * 512 + threadIdx.x;
    int i1 = i0 + 256;
    if (i1 < n4) {
        float4 x0 = __ldcs(a1 + i0);
        float4 x1 = __ldcs(a1 + i1);
        float4 y0 = __ldcs(a2 + i0);
        float4 y1 = __ldcs(a2 + i1);
        __stcs(out + i0, ds4(x0, y0));
        __stcs(out + i1, ds4(x1, y1));
    } else if (i0 < n4) {
        float4 x0 = __ldcs(a1 + i0);
        float4 y0 = __ldcs(a2 + i0);
        __stcs(out + i0, ds4(x0, y0));
    }
}

// Scalar tail for n % 4 != 0 (not hit for this shape; kept for safety).
__global__ void ds_combine_tail(
    const float* __restrict__ a1,
    const float* __restrict__ a2,
    float* __restrict__ out,
    int start, int n)
{
    int i = start + blockIdx.x * blockDim.x + threadIdx.x;
    if (i >= n) return;
    float x = a1[i], y = a2[i];
    out[i] = fmaf((x - 1.0f) * (y - 1.0f), INV_C, x + y - 1.0f);
}

extern "C" void kernel_launch(void* const* d_in, const int* in_sizes, int n_in,
                              void* d_out, int out_size)
{
    const float* a1 = (const float*)d_in[0];
    const float* a2 = (const float*)d_in[1];
    float* out = (float*)d_out;

    int n = out_size;          // 8*21*512*512 = 44,040,192
    int n4 = n >> 2;           // 11,010,048 float4

    const int threads = 256;
    const int f4_per_block = 512;

    if (n4 % f4_per_block == 0) {
        // One wave: 152 SMs x 8 blocks, grid-stride over 21504 chunks.
        const int blocks = 152 * 8;   // 1216
        ds_combine_wave<<<blocks, threads>>>(
            (const float4*)a1, (const float4*)a2, (float4*)out, n4);
    } else {
        int blocks = (n4 + f4_per_block - 1) / f4_per_block;
        ds_combine_guarded<<<blocks, threads>>>(
            (const float4*)a1, (const float4*)a2, (float4*)out, n4);
    }

    int tail_start = n4 << 2;
    if (n - tail_start > 0) {
        ds_combine_tail<<<1, 128>>>(a1, a2, out, tail_start, n);
    }
}

// round 6
// speedup vs baseline: 1.1009x; 1.1009x over previous
#include <cuda_runtime.h>

// DempsterSchaferCombine — algebraically reduced to a pure elementwise stream:
//   out = (a1-1)*(a2-1)/21 + a1 + a2 - 1
// (Dirichlet strengths S1,S2 and the conflict denom cancel exactly; rel_err
// vs the full reference path is ~8e-8.)
//
// R6: back to the hardware-scheduled one-shot grid (grid-stride loops measured
// 6-8% worse DRAM%), now with 256-bit ld/st (PTX ld.global.v8.f32, sm_100a+):
// each thread handles 8 consecutive floats per array, one warp instruction
// moves 1024B. Exact tiling: n8 = 5,505,024 = 21504 blocks * 256 threads.

#define INV_C (1.0f / 21.0f)

__device__ __forceinline__ void ld256_cs(const float* p, float v[8]) {
    asm volatile(
        "ld.global.cs.v8.f32 {%0,%1,%2,%3,%4,%5,%6,%7}, [%8];"
        : "=f"(v[0]), "=f"(v[1]), "=f"(v[2]), "=f"(v[3]),
          "=f"(v[4]), "=f"(v[5]), "=f"(v[6]), "=f"(v[7])
        : "l"(p));
}

__device__ __forceinline__ void st256_cs(float* p, const float v[8]) {
    asm volatile(
        "st.global.cs.v8.f32 [%0], {%1,%2,%3,%4,%5,%6,%7,%8};"
        :: "l"(p),
           "f"(v[0]), "f"(v[1]), "f"(v[2]), "f"(v[3]),
           "f"(v[4]), "f"(v[5]), "f"(v[6]), "f"(v[7])
        : "memory");
}

// Exact path: one 8-float chunk per thread, no predicates.
// Requires n % (256*8) == 0 and 32B-aligned pointers.
__global__ __launch_bounds__(256, 8) void ds_combine_v8(
    const float* __restrict__ a1,
    const float* __restrict__ a2,
    float* __restrict__ out)
{
    long long base = ((long long)blockIdx.x * 256 + threadIdx.x) * 8;

    float x[8], y[8], r[8];
    ld256_cs(a1 + base, x);
    ld256_cs(a2 + base, y);

#pragma unroll
    for (int k = 0; k < 8; k++)
        r[k] = fmaf((x[k] - 1.0f) * (y[k] - 1.0f), INV_C, x[k] + y[k] - 1.0f);

    st256_cs(out + base, r);
}

__device__ __forceinline__ float4 ds4(float4 x, float4 y) {
    float4 r;
    r.x = fmaf((x.x - 1.0f) * (y.x - 1.0f), INV_C, x.x + y.x - 1.0f);
    r.y = fmaf((x.y - 1.0f) * (y.y - 1.0f), INV_C, x.y + y.y - 1.0f);
    r.z = fmaf((x.z - 1.0f) * (y.z - 1.0f), INV_C, x.z + y.z - 1.0f);
    r.w = fmaf((x.w - 1.0f) * (y.w - 1.0f), INV_C, x.w + y.w - 1.0f);
    return r;
}

// Guarded fallback (float4) for shapes not divisible by 2048 floats/block.
__global__ __launch_bounds__(256, 8) void ds_combine_guarded(
    const float4* __restrict__ a1,
    const float4* __restrict__ a2,
    float4* __restrict__ out,
    int n4)
{
    int i0 = blockIdx.x * 512 + threadIdx.x;
    int i1 = i0 + 256;
    if (i1 < n4) {
        float4 x0 = __ldcs(a1 + i0);
        float4 x1 = __ldcs(a1 + i1);
        float4 y0 = __ldcs(a2 + i0);
        float4 y1 = __ldcs(a2 + i1);
        __stcs(out + i0, ds4(x0, y0));
        __stcs(out + i1, ds4(x1, y1));
    } else if (i0 < n4) {
        float4 x0 = __ldcs(a1 + i0);
        float4 y0 = __ldcs(a2 + i0);
        __stcs(out + i0, ds4(x0, y0));
    }
}

// Scalar tail for n % 4 != 0 (not hit for this shape; kept for safety).
__global__ void ds_combine_tail(
    const float* __restrict__ a1,
    const float* __restrict__ a2,
    float* __restrict__ out,
    int start, int n)
{
    int i = start + blockIdx.x * blockDim.x + threadIdx.x;
    if (i >= n) return;
    float x = a1[i], y = a2[i];
    out[i] = fmaf((x - 1.0f) * (y - 1.0f), INV_C, x + y - 1.0f);
}

extern "C" void kernel_launch(void* const* d_in, const int* in_sizes, int n_in,
                              void* d_out, int out_size)
{
    const float* a1 = (const float*)d_in[0];
    const float* a2 = (const float*)d_in[1];
    float* out = (float*)d_out;

    int n = out_size;                   // 8*21*512*512 = 44,040,192
    const int floats_per_block = 256 * 8;  // 2048

    if (n % floats_per_block == 0) {
        // This shape: 21504 blocks, branch-free, 256-bit ld/st.
        ds_combine_v8<<<n / floats_per_block, 256>>>(a1, a2, out);
    } else {
        int n4 = n >> 2;
        int blocks = (n4 + 511) / 512;
        ds_combine_guarded<<<blocks, 256>>>(
            (const float4*)a1, (const float4*)a2, (float4*)out, n4);
        int tail_start = n4 << 2;
        if (n - tail_start > 0)
            ds_combine_tail<<<1, 128>>>(a1, a2, out, tail_start, n);
    }
}